// round 1
// baseline (speedup 1.0000x reference)
#include <cuda_runtime.h>
#include <math.h>

#define NPART 512
#define NB    16
#define HIDN  100
#define WPB   8            // warps (particles i) per block
#define TPB   256

__device__ __forceinline__ float ex2f(float x) {
    float y; asm("ex2.approx.ftz.f32 %0, %1;" : "=f"(y) : "f"(x)); return y;
}
__device__ __forceinline__ float rsq_a(float x) {
    float y; asm("rsqrt.approx.ftz.f32 %0, %1;" : "=f"(y) : "f"(x)); return y;
}
__device__ __forceinline__ float rcp_a(float x) {
    float y; asm("rcp.approx.ftz.f32 %0, %1;" : "=f"(y) : "f"(x)); return y;
}

__global__ __launch_bounds__(TPB)
void vortex_fused_kernel(const float* __restrict__ inp,
                         const float* __restrict__ W1,
                         const float* __restrict__ b1,
                         const float* __restrict__ W2,
                         const float* __restrict__ b2,
                         float* __restrict__ out)
{
    // particle data (raw + derived), SoA for conflict-free LDS
    __shared__ float sy[NPART], sx[NPART], stau[NPART], ssig[NPART];
    __shared__ float sc[NPART], sd[NPART];
    __shared__ float st2p[NPART];   // tau / (2*pi)
    __shared__ float sis2[NPART];   // 1/sig^2
    __shared__ float sml2e[NPART];  // -log2e / sig^2
    __shared__ float smc[NPART];    // -c * log2e
    __shared__ float smd[NPART];    // -d * log2e
    // MLP weights
    __shared__ float sW1[10 * HIDN], sb1[HIDN], sW2[HIDN * 6], sb2v[6];

    const int tid  = threadIdx.x;
    const int bpb  = NPART / WPB;              // 64 blocks per batch
    const int b    = blockIdx.x / bpb;
    const int ig   = blockIdx.x % bpb;
    const int warp = tid >> 5;
    const int lane = tid & 31;
    const int i    = ig * WPB + warp;

    const float L2E    = 1.4426950408889634f;
    const float INV2PI = 0.15915494309189535f;

    // ---- cooperative load + per-particle precompute ----
    const float* binp = inp + (size_t)b * NPART * 6;
    for (int p = tid; p < NPART; p += TPB) {
        float y   = binp[p * 6 + 0];
        float x   = binp[p * 6 + 1];
        float tau = binp[p * 6 + 2];
        float sig = binp[p * 6 + 3];
        float c   = binp[p * 6 + 4];
        float d   = binp[p * 6 + 5];
        sy[p] = y;  sx[p] = x;  stau[p] = tau; ssig[p] = sig;
        sc[p] = c;  sd[p] = d;
        st2p[p]  = tau * INV2PI;
        float is2 = rcp_a(sig * sig);
        sis2[p]  = is2;
        sml2e[p] = -is2 * L2E;
        smc[p]   = -c * L2E;
        smd[p]   = -d * L2E;
    }
    for (int p = tid; p < 10 * HIDN; p += TPB) sW1[p] = W1[p];
    for (int p = tid; p < HIDN;      p += TPB) sb1[p] = b1[p];
    for (int p = tid; p < HIDN * 6;  p += TPB) sW2[p] = W2[p];
    if (tid < 6) sb2v[tid] = b2[tid];
    __syncthreads();

    // ---- all-pairs mainloop: one warp per i, lanes stride j ----
    const float yi = sy[i], xi = sx[i];
    float Svy = 0.f, Svx = 0.f, SF = 0.f, SG = 0.f, SGxx = 0.f, SGyy = 0.f;

    #pragma unroll 4
    for (int jj = 0; jj < NPART / 32; ++jj) {
        int j = jj * 32 + lane;
        float dy = yi - sy[j];
        float dx = xi - sx[j];
        float sq = fmaf(dy, dy, dx * dx);
        float s  = sq + 1e-6f;
        float rs = rsq_a(s);
        float r     = s * rs;
        float inv_s = rs * rs;                 // 1/s without an RCP
        float inv2r = 0.5f * rs;               // 1/(2r)
        float e1 = ex2f(sq * sml2e[j]);        // exp(-sq/sig^2)
        float e2 = ex2f(fmaf(smc[j], r, smd[j] * sq)); // exp(-c r - d sq)
        float g  = 1.0f - e1;                  // exactly 0 when j==i
        float gh = g * e2;
        float A  = st2p[j] * inv_s;            // tau/(2 pi s)
        float F  = A * gh;                     // falloff
        float t1 = (sis2[j] * e1) * e2;        // g' h
        float t2 = fmaf(sc[j], inv2r, sd[j] + inv_s); // c/(2r)+d+1/s
        float Fp = A * fmaf(-gh, t2, t1);      // dF/d(sq)
        float G2 = Fp + Fp;                    // 2 F'
        Svy  = fmaf(-F, dx, Svy);
        Svx  = fmaf( F, dy, Svx);
        SF  += F;
        float gdy = G2 * dy, gdx = G2 * dx;
        SG   = fmaf(gdy, dx, SG);
        SGxx = fmaf(gdx, dx, SGxx);
        SGyy = fmaf(gdy, dy, SGyy);
    }

    // ---- warp butterfly reduce (all lanes get totals; needed for MLP) ----
    #pragma unroll
    for (int o = 16; o; o >>= 1) {
        Svy  += __shfl_xor_sync(0xffffffffu, Svy,  o);
        Svx  += __shfl_xor_sync(0xffffffffu, Svx,  o);
        SF   += __shfl_xor_sync(0xffffffffu, SF,   o);
        SG   += __shfl_xor_sync(0xffffffffu, SG,   o);
        SGxx += __shfl_xor_sync(0xffffffffu, SGxx, o);
        SGyy += __shfl_xor_sync(0xffffffffu, SGyy, o);
    }

    // feature vector: tau, sig, c, d, vy, vx, dvy/dy, dvy/dx, dvx/dy, dvx/dx
    float feat[10];
    feat[0] = stau[i]; feat[1] = ssig[i]; feat[2] = sc[i]; feat[3] = sd[i];
    feat[4] = Svy;     feat[5] = Svx;
    feat[6] = -SG;             // dvy/dy
    feat[7] = -(SGxx + SF);    // dvy/dx
    feat[8] = SGyy + SF;       // dvx/dy
    feat[9] = SG;              // dvx/dx = -dvy/dy

    // ---- MLP 10 -> 100 (LeakyReLU 0.1) -> 6, lanes own hidden units ----
    float po[6] = {0.f, 0.f, 0.f, 0.f, 0.f, 0.f};
    #pragma unroll
    for (int rblk = 0; rblk < 4; ++rblk) {
        int k = rblk * 32 + lane;
        if (k < HIDN) {
            float h = sb1[k];
            #pragma unroll
            for (int f = 0; f < 10; ++f) h = fmaf(feat[f], sW1[f * HIDN + k], h);
            h = (h >= 0.0f) ? h : 0.1f * h;
            #pragma unroll
            for (int m = 0; m < 6; ++m) po[m] = fmaf(h, sW2[k * 6 + m], po[m]);
        }
    }
    #pragma unroll
    for (int o = 16; o; o >>= 1) {
        #pragma unroll
        for (int m = 0; m < 6; ++m)
            po[m] += __shfl_xor_sync(0xffffffffu, po[m], o);
    }

    // ---- epilogue ----
    if (lane == 0) {
        float o0 = po[0] + sb2v[0];
        float o1 = po[1] + sb2v[1];
        float o2 = po[2] + sb2v[2];
        float o3 = po[3] + sb2v[3];
        float o4 = po[4] + sb2v[4];
        float o5 = po[5] + sb2v[5];
        float* op = out + ((size_t)b * NPART + i) * 6;
        op[0] = yi      + 0.1f * o0;
        op[1] = xi      + 0.1f * o1;
        op[2] = feat[0] + 0.1f * o2;
        op[3] = feat[1] + 0.1f * o3;
        // numerically-stable softplus, matching jax.nn.softplus
        float sp4 = fmaxf(o4, 0.0f) + log1pf(expf(-fabsf(o4)));
        float sp5 = fmaxf(o5, 0.0f) + log1pf(expf(-fabsf(o5)));
        op[4] = 0.1f * sp4;
        op[5] = 0.1f * sp5;
    }
}

extern "C" void kernel_launch(void* const* d_in, const int* in_sizes, int n_in,
                              void* d_out, int out_size)
{
    const float* inp = (const float*)d_in[0];  // (16,512,6)
    const float* W1  = (const float*)d_in[1];  // (10,100)
    const float* b1  = (const float*)d_in[2];  // (100,)
    const float* W2  = (const float*)d_in[3];  // (100,6)
    const float* b2  = (const float*)d_in[4];  // (6,)
    float* out = (float*)d_out;                // (16,512,6)

    dim3 grid(NB * (NPART / WPB));             // 1024 blocks
    dim3 block(TPB);                           // 8 warps: 1 warp per particle i
    vortex_fused_kernel<<<grid, block>>>(inp, W1, b1, W2, b2, out);
}